// round 5
// baseline (speedup 1.0000x reference)
#include <cuda_runtime.h>

// Problem constants (match reference)
#define K_VOX 12000
#define T_PTS 35
#define F_IN  7
#define D_DIM 10
#define H_DIM 400
#define W_DIM 352
#define C_OUT_DIM 128
#define EPSVAL 1e-3f

// One resident wave: 148 SMs x 4 blocks of 256 threads.
#define NSM     148
#define OCC     4
#define NBLK    (NSM * OCC)            // 592
#define NC_SM   74                     // compute SMs (residues 0..73)
#define NCBLK   (NC_SM * OCC)          // 296 compute blocks
#define NZBLK   ((NSM - NC_SM) * OCC)  // 296 zero blocks
#define NGROUPS (NCBLK * 4)            // 1184 voxel groups
#define ZT      (NZBLK * 256)          // zero threads

// Voxel-wise results staged here (fully overwritten each launch).
__device__ float g_vox[K_VOX * C_OUT_DIM];   // 6.1 MB

#define GBAR(id) asm volatile("bar.sync %0, 64;" :: "r"(id) : "memory")

// ---------------------------------------------------------------------------
// Fat kernel, SM-specialized 74/74: half the SMs compute voxel features with
// valid-point compaction; the other half stream-zero the 720MB output at the
// HBM write floor. Compute hides completely under the write shadow.
// ---------------------------------------------------------------------------
__global__ __launch_bounds__(256, 4) void fat_kernel(
    const float* __restrict__ feat,     // [K, T, F]
    const float* __restrict__ w1,       // [F, 16]
    const float* __restrict__ b1,
    const float* __restrict__ gamma1, const float* __restrict__ beta1,
    const float* __restrict__ mean1,  const float* __restrict__ var1,
    const float* __restrict__ w2,       // [32, 64]
    const float* __restrict__ b2,
    const float* __restrict__ gamma2, const float* __restrict__ beta2,
    const float* __restrict__ mean2,  const float* __restrict__ var2,
    float*       __restrict__ out,      // [1, D, H, W, 128] — zeroed here
    int n4)                             // out_size / 4
{
    const int bid = blockIdx.x;
    const int tid = threadIdx.x;
    const int res = bid % NSM;

    if (res >= NC_SM) {
        // ---------------- Zero role (dedicated SMs) ----------------
        const int zb  = (bid / NSM) * (NSM - NC_SM) + (res - NC_SM);
        const int zid = zb * 256 + tid;
        float4* o4 = (float4*)out;
        const float4 z = make_float4(0.f, 0.f, 0.f, 0.f);
        for (int i = zid; i < n4; i += ZT) o4[i] = z;
        return;
    }

    // ---------------- Compute role (dedicated SMs) ----------------
    const int cb   = (bid / NSM) * NC_SM + res;  // compute block 0..295
    const int g    = tid >> 6;                   // group 0..3
    const int v    = tid & 63;                   // channel within group
    const int lane = v & 31;
    const int wg   = v >> 5;                     // warp within group (0/1)
    const int gidx = cb * 4 + g;                 // group id 0..1183

    __shared__ float sw1[F_IN * 16];
    __shared__ float sb1[16], ss1[16], so1[16], spw1b[16];
    __shared__ float sfeat[4][T_PTS * F_IN];
    __shared__ unsigned smb[4][2];               // ballot words (t<32, t>=32)
    __shared__ int   sidx[4][T_PTS];             // compacted valid t list
    __shared__ __align__(16) float pw1s[4][T_PTS * 16];  // compacted rows
    __shared__ float sagg1[4][16];

    // Block-invariant stage-1 params
    if (tid < F_IN * 16) sw1[tid] = w1[tid];
    if (tid < 16) {
        float s = gamma1[tid] * rsqrtf(var1[tid] + EPSVAL);
        float o = beta1[tid] - mean1[tid] * s;
        float bb = b1[tid];
        ss1[tid] = s; so1[tid] = o; sb1[tid] = bb;
        spw1b[tid] = fmaxf(bb, 0.f) * s + o;     // pw1 of a fully-masked point
    }

    // Per-thread stage-2 params (thread owns channels v and 64+v)
    const float s2v = gamma2[v] * rsqrtf(var2[v] + EPSVAL);
    const float o2v = beta2[v] - mean2[v] * s2v;
    const float b2v = b2[v];
    const float pw2b = fmaxf(b2v, 0.f) * s2v + o2v;  // pw2 of a masked point

    float w2A[16], w2B[16];
#pragma unroll
    for (int j = 0; j < 16; j++) {
        w2A[j] = __ldg(&w2[j * 64 + v]);
        w2B[j] = __ldg(&w2[(16 + j) * 64 + v]);
    }
    __syncthreads();   // params visible to all groups

    const int barid = g + 1;

    for (int k = gidx; k < K_VOX; k += NGROUPS) {
        // Load this voxel's point features
        for (int i = v; i < T_PTS * F_IN; i += 64)
            sfeat[g][i] = feat[k * (T_PTS * F_IN) + i];
        GBAR(barid);

        // Mask + ballot: point t valid iff max over its features != 0
        bool valid = false;
        if (v < T_PTS) {
            float m = sfeat[g][v * F_IN];
#pragma unroll
            for (int f = 1; f < F_IN; f++) m = fmaxf(m, sfeat[g][v * F_IN + f]);
            valid = (m != 0.f);
        }
        unsigned bal = __ballot_sync(0xffffffffu, valid);
        if (lane == 0) smb[g][wg] = bal;
        GBAR(barid);

        const unsigned b0 = smb[g][0], b1m = smb[g][1];
        const int nvalid = __popc(b0) + __popc(b1m);

        // Write compacted index list: rank of each valid t
        if (valid) {
            int r = (wg == 0)
                  ? __popc(b0 & ((1u << lane) - 1u))
                  : __popc(b0) + __popc(b1m & ((1u << lane) - 1u));
            sidx[g][r] = v;   // t == v for valid threads
        }
        GBAR(barid);

        // Stage 1 over compacted valid rows only
        for (int e = v; e < nvalid * 16; e += 64) {
            const int i = e >> 4, u = e & 15;
            const int t = sidx[g][i];
            float d = sb1[u];
#pragma unroll
            for (int f = 0; f < F_IN; f++)
                d = fmaf(sfeat[g][t * F_IN + f], sw1[f * 16 + u], d);
            pw1s[g][e] = fmaxf(d, 0.f) * ss1[u] + so1[u];
        }
        GBAR(barid);

        // agg1[u] = max over all t of pw1_eff: valid rows + constant for masked
        if (v < 16) {
            float m = (nvalid < T_PTS) ? spw1b[v] : -3.4e38f;
            for (int i = 0; i < nvalid; i++) m = fmaxf(m, pw1s[g][i * 16 + v]);
            sagg1[g][v] = m;
        }
        GBAR(barid);

        // Stage 2: per-channel dot over compacted rows (no branches)
        float aggdot = 0.f;
#pragma unroll
        for (int j = 0; j < 16; j++) aggdot = fmaf(sagg1[g][j], w2B[j], aggdot);
        const float base2 = b2v + aggdot;

        float m2 = -3.4e38f;
        for (int i = 0; i < nvalid; i++) {
            const float4* row = (const float4*)(pw1s[g] + i * 16);
            float4 r0 = row[0], r1 = row[1], r2 = row[2], r3 = row[3];
            float d0 = base2, d1 = 0.f;
            d0 = fmaf(r0.x, w2A[0], d0);  d1 = fmaf(r0.y, w2A[1], d1);
            d0 = fmaf(r0.z, w2A[2], d0);  d1 = fmaf(r0.w, w2A[3], d1);
            d0 = fmaf(r1.x, w2A[4], d0);  d1 = fmaf(r1.y, w2A[5], d1);
            d0 = fmaf(r1.z, w2A[6], d0);  d1 = fmaf(r1.w, w2A[7], d1);
            d0 = fmaf(r2.x, w2A[8], d0);  d1 = fmaf(r2.y, w2A[9], d1);
            d0 = fmaf(r2.z, w2A[10], d0); d1 = fmaf(r2.w, w2A[11], d1);
            d0 = fmaf(r3.x, w2A[12], d0); d1 = fmaf(r3.y, w2A[13], d1);
            d0 = fmaf(r3.z, w2A[14], d0); d1 = fmaf(r3.w, w2A[15], d1);
            m2 = fmaxf(m2, fmaxf(d0 + d1, 0.f) * s2v + o2v);
        }

        float outA, outB;
        if (nvalid == 0) {
            outA = 0.f; outB = 0.f;
        } else if (nvalid < T_PTS) {
            outA = fmaxf(m2, 0.f);                    // masked rows give 0
            outB = fmaxf(fmaxf(m2, pw2b), 0.f);       // agg includes pw2b
        } else {
            outA = m2; outB = m2;
        }

        g_vox[k * C_OUT_DIM + v]      = outA;
        g_vox[k * C_OUT_DIM + 64 + v] = outB;
        GBAR(barid);   // smem reuse next voxel
    }
}

// ---------------------------------------------------------------------------
// Scatter-add staged voxel results into the (now zeroed) grid.
// ---------------------------------------------------------------------------
__global__ __launch_bounds__(256) void scatter_kernel(
    const int* __restrict__ coord,      // [K, 4]
    float*     __restrict__ out)
{
    const int i = blockIdx.x * 256 + threadIdx.x;   // 0 .. K*128-1
    const int k = i >> 7;
    const int c = i & 127;
    const int4 cc = __ldg(&((const int4*)coord)[k]);
    const int base =
        (((cc.x * D_DIM + cc.y) * H_DIM + cc.z) * W_DIM + cc.w) * C_OUT_DIM;
    atomicAdd(out + base + c, g_vox[i]);
}

// ---------------------------------------------------------------------------
extern "C" void kernel_launch(void* const* d_in, const int* in_sizes, int n_in,
                              void* d_out, int out_size) {
    const float* feat   = (const float*)d_in[0];
    const float* w1     = (const float*)d_in[1];
    const float* b1     = (const float*)d_in[2];
    const float* gamma1 = (const float*)d_in[3];
    const float* beta1  = (const float*)d_in[4];
    const float* mean1  = (const float*)d_in[5];
    const float* var1   = (const float*)d_in[6];
    const float* w2     = (const float*)d_in[7];
    const float* b2     = (const float*)d_in[8];
    const float* gamma2 = (const float*)d_in[9];
    const float* beta2  = (const float*)d_in[10];
    const float* mean2  = (const float*)d_in[11];
    const float* var2   = (const float*)d_in[12];
    const int*   coord  = (const int*)d_in[13];
    float* out = (float*)d_out;

    const int n4 = out_size / 4;
    fat_kernel<<<NBLK, 256>>>(feat, w1, b1, gamma1, beta1, mean1, var1,
                              w2, b2, gamma2, beta2, mean2, var2,
                              out, n4);
    scatter_kernel<<<(K_VOX * C_OUT_DIM) / 256, 256>>>(coord, out);
}

// round 6
// speedup vs baseline: 1.1510x; 1.1510x over previous
#include <cuda_runtime.h>

// Problem constants (match reference)
#define K_VOX 12000
#define T_PTS 35
#define F_IN  7
#define D_DIM 10
#define H_DIM 400
#define W_DIM 352
#define C_OUT_DIM 128
#define EPSVAL 1e-3f

// Exactly one resident wave: 148 SMs x 4 blocks x 256 threads.
#define NSM     148
#define NBLK    (NSM * 4)          // 592 blocks
#define NCBLK   (NBLK / 2)         // 296 compute blocks (even bids)
#define NZBLK   (NBLK / 2)         // 296 zero blocks   (odd bids)
#define NGROUPS (NCBLK * 4)        // 1184 voxel groups
#define ZT      (NZBLK * 256)      // zero lanes

// Voxel-wise results staged here (fully overwritten each launch).
__device__ float g_vox[K_VOX * C_OUT_DIM];   // 6.1 MB

#define GBAR(id) asm volatile("bar.sync %0, 64;" :: "r"(id) : "memory")

// ---------------------------------------------------------------------------
// Fat kernel, one wave: even blocks compute (4 independent 64-thread voxel
// groups, ~10 voxels grid-stride each); odd blocks stream-zero the 720MB
// output. Both roles co-resident on every SM; compute hides under HBM writes.
// ---------------------------------------------------------------------------
__global__ __launch_bounds__(256, 4) void fat_kernel(
    const float* __restrict__ feat,     // [K, T, F]
    const float* __restrict__ w1,       // [F, 16]
    const float* __restrict__ b1,
    const float* __restrict__ gamma1, const float* __restrict__ beta1,
    const float* __restrict__ mean1,  const float* __restrict__ var1,
    const float* __restrict__ w2,       // [32, 64]
    const float* __restrict__ b2,
    const float* __restrict__ gamma2, const float* __restrict__ beta2,
    const float* __restrict__ mean2,  const float* __restrict__ var2,
    float*       __restrict__ out,      // [1, D, H, W, 128] — zeroed here
    int n4)                             // out_size / 4
{
    const int bid = blockIdx.x;
    const int tid = threadIdx.x;

    if (bid & 1) {
        // ---------------- Zero role ----------------
        const int zid = (bid >> 1) * 256 + tid;
        float4* o4 = (float4*)out;
        const float4 z = make_float4(0.f, 0.f, 0.f, 0.f);
        for (int i = zid; i < n4; i += ZT) o4[i] = z;
        return;
    }

    // ---------------- Compute role ----------------
    const int cb   = bid >> 1;          // compute block 0..295
    const int g    = tid >> 6;          // group 0..3
    const int v    = tid & 63;          // channel within group
    const int gidx = cb * 4 + g;        // group id 0..1183

    __shared__ float sw1[F_IN * 16];
    __shared__ float sb1[16], ss1[16], so1[16], spw1b[16];
    __shared__ float sfeat[4][T_PTS * F_IN];
    __shared__ int   smask[4][T_PTS];
    __shared__ __align__(16) float pw1s[4][T_PTS * 16];
    __shared__ float sagg1[4][16];

    // Block-invariant stage-1 params
    if (tid < F_IN * 16) sw1[tid] = w1[tid];
    if (tid < 16) {
        float s = gamma1[tid] * rsqrtf(var1[tid] + EPSVAL);
        float o = beta1[tid] - mean1[tid] * s;
        float bb = b1[tid];
        ss1[tid] = s; so1[tid] = o; sb1[tid] = bb;
        spw1b[tid] = fmaxf(bb, 0.f) * s + o;     // pw1 of a fully-masked point
    }

    // Per-thread stage-2 params (thread owns channels v and 64+v)
    const float s2v = gamma2[v] * rsqrtf(var2[v] + EPSVAL);
    const float o2v = beta2[v] - mean2[v] * s2v;
    const float b2v = b2[v];
    const float pw2b = fmaxf(b2v, 0.f) * s2v + o2v;   // pw2 of a masked point

    float w2A[16], w2B[16];
#pragma unroll
    for (int j = 0; j < 16; j++) {
        w2A[j] = __ldg(&w2[j * 64 + v]);
        w2B[j] = __ldg(&w2[(16 + j) * 64 + v]);
    }
    __syncthreads();   // params visible to all groups

    const int barid = g + 1;   // named barrier per 64-thread group

    for (int k = gidx; k < K_VOX; k += NGROUPS) {
        // Load this voxel's point features
        for (int i = v; i < T_PTS * F_IN; i += 64)
            sfeat[g][i] = feat[k * (T_PTS * F_IN) + i];
        GBAR(barid);

        // Mask: point valid iff max over its features != 0
        if (v < T_PTS) {
            float m = sfeat[g][v * F_IN];
#pragma unroll
            for (int f = 1; f < F_IN; f++) m = fmaxf(m, sfeat[g][v * F_IN + f]);
            smask[g][v] = (m != 0.f) ? 1 : 0;
        }
        GBAR(barid);

        // Stage 1: pw1_eff[t][u] (masked rows take the constant pw1b[u])
        for (int e = v; e < T_PTS * 16; e += 64) {
            const int t = e >> 4, u = e & 15;
            float val;
            if (smask[g][t]) {
                float d = sb1[u];
#pragma unroll
                for (int f = 0; f < F_IN; f++)
                    d = fmaf(sfeat[g][t * F_IN + f], sw1[f * 16 + u], d);
                val = fmaxf(d, 0.f) * ss1[u] + so1[u];
            } else {
                val = spw1b[u];
            }
            pw1s[g][e] = val;
        }
        GBAR(barid);

        // agg1[u] = max over ALL t of pw1_eff (reference maxes pre-mask)
        if (v < 16) {
            float m = pw1s[g][v];
            for (int t = 1; t < T_PTS; t++) m = fmaxf(m, pw1s[g][t * 16 + v]);
            sagg1[g][v] = m;
        }
        GBAR(barid);

        // Stage 2: per-channel dot over valid rows
        float aggdot = 0.f;
#pragma unroll
        for (int j = 0; j < 16; j++) aggdot = fmaf(sagg1[g][j], w2B[j], aggdot);
        const float base2 = b2v + aggdot;

        float vmax = -3.4e38f, amax = -3.4e38f;
        int anyInvalid = 0, anyValid = 0;
        for (int t = 0; t < T_PTS; t++) {
            if (smask[g][t]) {
                anyValid = 1;
                const float4* row = (const float4*)(pw1s[g] + t * 16);
                float4 r0 = row[0], r1 = row[1], r2 = row[2], r3 = row[3];
                float d0 = base2, d1 = 0.f;
                d0 = fmaf(r0.x, w2A[0], d0);  d1 = fmaf(r0.y, w2A[1], d1);
                d0 = fmaf(r0.z, w2A[2], d0);  d1 = fmaf(r0.w, w2A[3], d1);
                d0 = fmaf(r1.x, w2A[4], d0);  d1 = fmaf(r1.y, w2A[5], d1);
                d0 = fmaf(r1.z, w2A[6], d0);  d1 = fmaf(r1.w, w2A[7], d1);
                d0 = fmaf(r2.x, w2A[8], d0);  d1 = fmaf(r2.y, w2A[9], d1);
                d0 = fmaf(r2.z, w2A[10], d0); d1 = fmaf(r2.w, w2A[11], d1);
                d0 = fmaf(r3.x, w2A[12], d0); d1 = fmaf(r3.y, w2A[13], d1);
                d0 = fmaf(r3.z, w2A[14], d0); d1 = fmaf(r3.w, w2A[15], d1);
                float pw2 = fmaxf(d0 + d1, 0.f) * s2v + o2v;
                vmax = fmaxf(vmax, pw2);
                amax = fmaxf(amax, pw2);
            } else {
                anyInvalid = 1;
            }
        }

        float outA, outB;
        if (!anyValid) {
            outA = 0.f; outB = 0.f;
        } else if (anyInvalid) {
            amax = fmaxf(amax, pw2b);
            outA = fmaxf(vmax, 0.f);
            outB = fmaxf(amax, 0.f);
        } else {
            outA = vmax; outB = amax;
        }

        g_vox[k * C_OUT_DIM + v]      = outA;
        g_vox[k * C_OUT_DIM + 64 + v] = outB;
        GBAR(barid);   // smem reuse next voxel
    }
}

// ---------------------------------------------------------------------------
// Scatter-add staged voxel results into the (now zeroed) grid.
// ---------------------------------------------------------------------------
__global__ __launch_bounds__(256) void scatter_kernel(
    const int* __restrict__ coord,      // [K, 4]
    float*     __restrict__ out)
{
    const int i = blockIdx.x * 256 + threadIdx.x;   // 0 .. K*128-1
    const int k = i >> 7;
    const int c = i & 127;
    const int4 cc = __ldg(&((const int4*)coord)[k]);
    const int base =
        (((cc.x * D_DIM + cc.y) * H_DIM + cc.z) * W_DIM + cc.w) * C_OUT_DIM;
    atomicAdd(out + base + c, g_vox[i]);
}

// ---------------------------------------------------------------------------
extern "C" void kernel_launch(void* const* d_in, const int* in_sizes, int n_in,
                              void* d_out, int out_size) {
    const float* feat   = (const float*)d_in[0];
    const float* w1     = (const float*)d_in[1];
    const float* b1     = (const float*)d_in[2];
    const float* gamma1 = (const float*)d_in[3];
    const float* beta1  = (const float*)d_in[4];
    const float* mean1  = (const float*)d_in[5];
    const float* var1   = (const float*)d_in[6];
    const float* w2     = (const float*)d_in[7];
    const float* b2     = (const float*)d_in[8];
    const float* gamma2 = (const float*)d_in[9];
    const float* beta2  = (const float*)d_in[10];
    const float* mean2  = (const float*)d_in[11];
    const float* var2   = (const float*)d_in[12];
    const int*   coord  = (const int*)d_in[13];
    float* out = (float*)d_out;

    const int n4 = out_size / 4;
    fat_kernel<<<NBLK, 256>>>(feat, w1, b1, gamma1, beta1, mean1, var1,
                              w2, b2, gamma2, beta2, mean2, var2,
                              out, n4);
    scatter_kernel<<<(K_VOX * C_OUT_DIM) / 256, 256>>>(coord, out);
}

// round 7
// speedup vs baseline: 1.9619x; 1.7045x over previous
#include <cuda_runtime.h>

// Problem constants (match reference)
#define K_VOX 12000
#define T_PTS 35
#define F_IN  7
#define D_DIM 10
#define H_DIM 400
#define W_DIM 352
#define C_OUT_DIM 128
#define EPSVAL 1e-3f

#define NZBLK 592                  // one-wave zero grid: 148 SMs x 4 blocks
#define ZT    (NZBLK * 256)        // zero threads
#define NCBLK 3000                 // compute blocks (4 voxels each)

// Voxel-wise results staged here (fully overwritten each launch).
__device__ float g_vox[K_VOX * C_OUT_DIM];   // 6.1 MB

// ---------------------------------------------------------------------------
// Kernel A (primary): one-wave persistent zero of the 720MB output.
// Fires the PDL trigger immediately so the compute kernel launches at t~0
// and overlaps with the HBM write stream.
// ---------------------------------------------------------------------------
__global__ __launch_bounds__(256, 8) void zero_kernel(float4* __restrict__ out,
                                                      int n4) {
    asm volatile("griddepcontrol.launch_dependents;" ::: "memory");
    const int zid = blockIdx.x * 256 + threadIdx.x;
    const float4 z = make_float4(0.f, 0.f, 0.f, 0.f);
    for (int i = zid; i < n4; i += ZT) out[i] = z;
}

// ---------------------------------------------------------------------------
// Kernel B (PDL secondary): VFE compute into g_vox. Exact R2-proven body:
// 3000 blocks x 256 threads, 4 independent 64-thread groups, 1 voxel each.
// Disjoint from zero_kernel's output, so no griddepcontrol.wait needed.
// ---------------------------------------------------------------------------
__global__ __launch_bounds__(256) void compute_kernel(
    const float* __restrict__ feat,     // [K, T, F]
    const float* __restrict__ w1,       // [F, 16]
    const float* __restrict__ b1,
    const float* __restrict__ gamma1, const float* __restrict__ beta1,
    const float* __restrict__ mean1,  const float* __restrict__ var1,
    const float* __restrict__ w2,       // [32, 64]
    const float* __restrict__ b2,
    const float* __restrict__ gamma2, const float* __restrict__ beta2,
    const float* __restrict__ mean2,  const float* __restrict__ var2)
{
    const int tid = threadIdx.x;
    const int g   = tid >> 6;                   // group 0..3
    const int v   = tid & 63;                   // channel within group
    const int k   = blockIdx.x * 4 + g;         // voxel id

    __shared__ float sw1[F_IN * 16];
    __shared__ float sb1[16], ss1[16], so1[16], spw1b[16];
    __shared__ float sfeat[4][T_PTS * F_IN];
    __shared__ int   smask[4][T_PTS];
    __shared__ __align__(16) float pw1s[4][T_PTS * 16];
    __shared__ float sagg1[4][16];

    // Block-invariant stage-1 params
    if (tid < F_IN * 16) sw1[tid] = w1[tid];
    if (tid < 16) {
        float s = gamma1[tid] * rsqrtf(var1[tid] + EPSVAL);
        float o = beta1[tid] - mean1[tid] * s;
        float bb = b1[tid];
        ss1[tid] = s; so1[tid] = o; sb1[tid] = bb;
        spw1b[tid] = fmaxf(bb, 0.f) * s + o;    // pw1 of a fully-masked point
    }

    // Per-thread stage-2 params (thread owns channels v and 64+v)
    const float s2v = gamma2[v] * rsqrtf(var2[v] + EPSVAL);
    const float o2v = beta2[v] - mean2[v] * s2v;
    const float b2v = b2[v];
    const float pw2b = fmaxf(b2v, 0.f) * s2v + o2v;   // pw2 of a masked point

    float w2A[16], w2B[16];
#pragma unroll
    for (int j = 0; j < 16; j++) {
        w2A[j] = __ldg(&w2[j * 64 + v]);
        w2B[j] = __ldg(&w2[(16 + j) * 64 + v]);
    }

    // Load this group's point features
    for (int i = v; i < T_PTS * F_IN; i += 64)
        sfeat[g][i] = feat[k * (T_PTS * F_IN) + i];
    __syncthreads();

    // Mask: point valid iff max over its features != 0
    if (v < T_PTS) {
        float m = sfeat[g][v * F_IN];
#pragma unroll
        for (int f = 1; f < F_IN; f++) m = fmaxf(m, sfeat[g][v * F_IN + f]);
        smask[g][v] = (m != 0.f) ? 1 : 0;
    }
    __syncthreads();

    // Stage 1: pw1_eff[t][u] (masked rows take the constant pw1b[u])
    for (int e = v; e < T_PTS * 16; e += 64) {
        const int t = e >> 4, u = e & 15;
        float val;
        if (smask[g][t]) {
            float d = sb1[u];
#pragma unroll
            for (int f = 0; f < F_IN; f++)
                d = fmaf(sfeat[g][t * F_IN + f], sw1[f * 16 + u], d);
            val = fmaxf(d, 0.f) * ss1[u] + so1[u];
        } else {
            val = spw1b[u];
        }
        pw1s[g][e] = val;
    }
    __syncthreads();

    // agg1[u] = max over ALL t of pw1_eff (reference maxes pre-mask)
    if (v < 16) {
        float m = pw1s[g][v];
        for (int t = 1; t < T_PTS; t++) m = fmaxf(m, pw1s[g][t * 16 + v]);
        sagg1[g][v] = m;
    }
    __syncthreads();

    // Stage 2: per-channel dot over valid rows
    float aggdot = 0.f;
#pragma unroll
    for (int j = 0; j < 16; j++) aggdot = fmaf(sagg1[g][j], w2B[j], aggdot);
    const float base2 = b2v + aggdot;

    float vmax = -3.4e38f, amax = -3.4e38f;
    int anyInvalid = 0, anyValid = 0;
    for (int t = 0; t < T_PTS; t++) {
        if (smask[g][t]) {
            anyValid = 1;
            const float4* row = (const float4*)(pw1s[g] + t * 16);
            float4 r0 = row[0], r1 = row[1], r2 = row[2], r3 = row[3];
            float d0 = base2, d1 = 0.f;
            d0 = fmaf(r0.x, w2A[0], d0);  d1 = fmaf(r0.y, w2A[1], d1);
            d0 = fmaf(r0.z, w2A[2], d0);  d1 = fmaf(r0.w, w2A[3], d1);
            d0 = fmaf(r1.x, w2A[4], d0);  d1 = fmaf(r1.y, w2A[5], d1);
            d0 = fmaf(r1.z, w2A[6], d0);  d1 = fmaf(r1.w, w2A[7], d1);
            d0 = fmaf(r2.x, w2A[8], d0);  d1 = fmaf(r2.y, w2A[9], d1);
            d0 = fmaf(r2.z, w2A[10], d0); d1 = fmaf(r2.w, w2A[11], d1);
            d0 = fmaf(r3.x, w2A[12], d0); d1 = fmaf(r3.y, w2A[13], d1);
            d0 = fmaf(r3.z, w2A[14], d0); d1 = fmaf(r3.w, w2A[15], d1);
            float pw2 = fmaxf(d0 + d1, 0.f) * s2v + o2v;
            vmax = fmaxf(vmax, pw2);
            amax = fmaxf(amax, pw2);
        } else {
            anyInvalid = 1;
        }
    }

    float outA, outB;
    if (!anyValid) {
        outA = 0.f; outB = 0.f;
    } else if (anyInvalid) {
        amax = fmaxf(amax, pw2b);
        outA = fmaxf(vmax, 0.f);
        outB = fmaxf(amax, 0.f);
    } else {
        outA = vmax; outB = amax;
    }

    g_vox[k * C_OUT_DIM + v]      = outA;
    g_vox[k * C_OUT_DIM + 64 + v] = outB;
}

// ---------------------------------------------------------------------------
// Kernel C: scatter-add staged voxel results into the (now zeroed) grid.
// Normal launch -> stream-depends on BOTH zero and compute.
// ---------------------------------------------------------------------------
__global__ __launch_bounds__(256) void scatter_kernel(
    const int* __restrict__ coord,      // [K, 4]
    float*     __restrict__ out)
{
    const int i = blockIdx.x * 256 + threadIdx.x;   // 0 .. K*128-1
    const int k = i >> 7;
    const int c = i & 127;
    const int4 cc = __ldg(&((const int4*)coord)[k]);
    const int base =
        (((cc.x * D_DIM + cc.y) * H_DIM + cc.z) * W_DIM + cc.w) * C_OUT_DIM;
    atomicAdd(out + base + c, g_vox[i]);
}

// ---------------------------------------------------------------------------
extern "C" void kernel_launch(void* const* d_in, const int* in_sizes, int n_in,
                              void* d_out, int out_size) {
    const float* feat   = (const float*)d_in[0];
    const float* w1     = (const float*)d_in[1];
    const float* b1     = (const float*)d_in[2];
    const float* gamma1 = (const float*)d_in[3];
    const float* beta1  = (const float*)d_in[4];
    const float* mean1  = (const float*)d_in[5];
    const float* var1   = (const float*)d_in[6];
    const float* w2     = (const float*)d_in[7];
    const float* b2     = (const float*)d_in[8];
    const float* gamma2 = (const float*)d_in[9];
    const float* beta2  = (const float*)d_in[10];
    const float* mean2  = (const float*)d_in[11];
    const float* var2   = (const float*)d_in[12];
    const int*   coord  = (const int*)d_in[13];
    float* out = (float*)d_out;

    const int n4 = out_size / 4;

    // Primary: one-wave zero kernel (triggers dependents immediately).
    zero_kernel<<<NZBLK, 256>>>((float4*)out, n4);

    // Secondary: compute kernel with programmatic stream serialization ->
    // launches while zero_kernel is still running (overlap).
    cudaLaunchConfig_t cfg = {};
    cfg.gridDim  = dim3(NCBLK, 1, 1);
    cfg.blockDim = dim3(256, 1, 1);
    cfg.dynamicSmemBytes = 0;
    cfg.stream = 0;
    cudaLaunchAttribute attr[1];
    attr[0].id = cudaLaunchAttributeProgrammaticStreamSerialization;
    attr[0].val.programmaticStreamSerializationAllowed = 1;
    cfg.attrs = attr;
    cfg.numAttrs = 1;
    cudaLaunchKernelEx(&cfg, compute_kernel,
                       feat, w1, b1, gamma1, beta1, mean1, var1,
                       w2, b2, gamma2, beta2, mean2, var2);

    // Scatter: normal launch, waits for both prior kernels.
    scatter_kernel<<<(K_VOX * C_OUT_DIM) / 256, 256>>>(coord, out);
}

// round 8
// speedup vs baseline: 1.9751x; 1.0067x over previous
#include <cuda_runtime.h>

// Problem constants (match reference)
#define K_VOX 12000
#define T_PTS 35
#define F_IN  7
#define D_DIM 10
#define H_DIM 400
#define W_DIM 352
#define C_OUT_DIM 128
#define EPSVAL 1e-3f

#define NZBLK 4736                 // zero grid: proven ~7.2 TB/s configuration
#define NCBLK 3000                 // compute blocks (4 voxels each)

// Voxel-wise results staged here (fully overwritten each launch).
__device__ float g_vox[K_VOX * C_OUT_DIM];   // 6.1 MB

// ---------------------------------------------------------------------------
// Zero kernel: stream 720MB of zeros at the HBM write floor (needs ~1.2M
// threads of store MLP — 4736 blocks x 256).
// ---------------------------------------------------------------------------
__global__ __launch_bounds__(256, 8) void zero_kernel(float4* __restrict__ out,
                                                      int n4) {
    int i = blockIdx.x * blockDim.x + threadIdx.x;
    const int stride = gridDim.x * blockDim.x;
    const float4 z = make_float4(0.f, 0.f, 0.f, 0.f);
    for (; i < n4; i += stride) out[i] = z;
}

// ---------------------------------------------------------------------------
// Compute kernel (parallel graph branch): VFE into g_vox. Proven R2 body:
// 3000 blocks x 256 threads, 4 independent 64-thread groups, 1 voxel each.
// ---------------------------------------------------------------------------
__global__ __launch_bounds__(256) void compute_kernel(
    const float* __restrict__ feat,     // [K, T, F]
    const float* __restrict__ w1,       // [F, 16]
    const float* __restrict__ b1,
    const float* __restrict__ gamma1, const float* __restrict__ beta1,
    const float* __restrict__ mean1,  const float* __restrict__ var1,
    const float* __restrict__ w2,       // [32, 64]
    const float* __restrict__ b2,
    const float* __restrict__ gamma2, const float* __restrict__ beta2,
    const float* __restrict__ mean2,  const float* __restrict__ var2)
{
    const int tid = threadIdx.x;
    const int g   = tid >> 6;                   // group 0..3
    const int v   = tid & 63;                   // channel within group
    const int k   = blockIdx.x * 4 + g;         // voxel id

    __shared__ float sw1[F_IN * 16];
    __shared__ float sb1[16], ss1[16], so1[16], spw1b[16];
    __shared__ float sfeat[4][T_PTS * F_IN];
    __shared__ int   smask[4][T_PTS];
    __shared__ __align__(16) float pw1s[4][T_PTS * 16];
    __shared__ float sagg1[4][16];

    // Block-invariant stage-1 params
    if (tid < F_IN * 16) sw1[tid] = w1[tid];
    if (tid < 16) {
        float s = gamma1[tid] * rsqrtf(var1[tid] + EPSVAL);
        float o = beta1[tid] - mean1[tid] * s;
        float bb = b1[tid];
        ss1[tid] = s; so1[tid] = o; sb1[tid] = bb;
        spw1b[tid] = fmaxf(bb, 0.f) * s + o;    // pw1 of a fully-masked point
    }

    // Per-thread stage-2 params (thread owns channels v and 64+v)
    const float s2v = gamma2[v] * rsqrtf(var2[v] + EPSVAL);
    const float o2v = beta2[v] - mean2[v] * s2v;
    const float b2v = b2[v];
    const float pw2b = fmaxf(b2v, 0.f) * s2v + o2v;   // pw2 of a masked point

    float w2A[16], w2B[16];
#pragma unroll
    for (int j = 0; j < 16; j++) {
        w2A[j] = __ldg(&w2[j * 64 + v]);
        w2B[j] = __ldg(&w2[(16 + j) * 64 + v]);
    }

    // Load this group's point features
    for (int i = v; i < T_PTS * F_IN; i += 64)
        sfeat[g][i] = feat[k * (T_PTS * F_IN) + i];
    __syncthreads();

    // Mask: point valid iff max over its features != 0
    if (v < T_PTS) {
        float m = sfeat[g][v * F_IN];
#pragma unroll
        for (int f = 1; f < F_IN; f++) m = fmaxf(m, sfeat[g][v * F_IN + f]);
        smask[g][v] = (m != 0.f) ? 1 : 0;
    }
    __syncthreads();

    // Stage 1: pw1_eff[t][u] (masked rows take the constant pw1b[u])
    for (int e = v; e < T_PTS * 16; e += 64) {
        const int t = e >> 4, u = e & 15;
        float val;
        if (smask[g][t]) {
            float d = sb1[u];
#pragma unroll
            for (int f = 0; f < F_IN; f++)
                d = fmaf(sfeat[g][t * F_IN + f], sw1[f * 16 + u], d);
            val = fmaxf(d, 0.f) * ss1[u] + so1[u];
        } else {
            val = spw1b[u];
        }
        pw1s[g][e] = val;
    }
    __syncthreads();

    // agg1[u] = max over ALL t of pw1_eff (reference maxes pre-mask)
    if (v < 16) {
        float m = pw1s[g][v];
        for (int t = 1; t < T_PTS; t++) m = fmaxf(m, pw1s[g][t * 16 + v]);
        sagg1[g][v] = m;
    }
    __syncthreads();

    // Stage 2: per-channel dot over valid rows
    float aggdot = 0.f;
#pragma unroll
    for (int j = 0; j < 16; j++) aggdot = fmaf(sagg1[g][j], w2B[j], aggdot);
    const float base2 = b2v + aggdot;

    float vmax = -3.4e38f, amax = -3.4e38f;
    int anyInvalid = 0, anyValid = 0;
    for (int t = 0; t < T_PTS; t++) {
        if (smask[g][t]) {
            anyValid = 1;
            const float4* row = (const float4*)(pw1s[g] + t * 16);
            float4 r0 = row[0], r1 = row[1], r2 = row[2], r3 = row[3];
            float d0 = base2, d1 = 0.f;
            d0 = fmaf(r0.x, w2A[0], d0);  d1 = fmaf(r0.y, w2A[1], d1);
            d0 = fmaf(r0.z, w2A[2], d0);  d1 = fmaf(r0.w, w2A[3], d1);
            d0 = fmaf(r1.x, w2A[4], d0);  d1 = fmaf(r1.y, w2A[5], d1);
            d0 = fmaf(r1.z, w2A[6], d0);  d1 = fmaf(r1.w, w2A[7], d1);
            d0 = fmaf(r2.x, w2A[8], d0);  d1 = fmaf(r2.y, w2A[9], d1);
            d0 = fmaf(r2.z, w2A[10], d0); d1 = fmaf(r2.w, w2A[11], d1);
            d0 = fmaf(r3.x, w2A[12], d0); d1 = fmaf(r3.y, w2A[13], d1);
            d0 = fmaf(r3.z, w2A[14], d0); d1 = fmaf(r3.w, w2A[15], d1);
            float pw2 = fmaxf(d0 + d1, 0.f) * s2v + o2v;
            vmax = fmaxf(vmax, pw2);
            amax = fmaxf(amax, pw2);
        } else {
            anyInvalid = 1;
        }
    }

    float outA, outB;
    if (!anyValid) {
        outA = 0.f; outB = 0.f;
    } else if (anyInvalid) {
        amax = fmaxf(amax, pw2b);
        outA = fmaxf(vmax, 0.f);
        outB = fmaxf(amax, 0.f);
    } else {
        outA = vmax; outB = amax;
    }

    g_vox[k * C_OUT_DIM + v]      = outA;
    g_vox[k * C_OUT_DIM + 64 + v] = outB;
}

// ---------------------------------------------------------------------------
// Scatter-add staged voxel results into the (now zeroed) grid.
// Runs after the join -> depends on BOTH branches.
// ---------------------------------------------------------------------------
__global__ __launch_bounds__(256) void scatter_kernel(
    const int* __restrict__ coord,      // [K, 4]
    float*     __restrict__ out)
{
    const int i = blockIdx.x * 256 + threadIdx.x;   // 0 .. K*128-1
    const int k = i >> 7;
    const int c = i & 127;
    const int4 cc = __ldg(&((const int4*)coord)[k]);
    const int base =
        (((cc.x * D_DIM + cc.y) * H_DIM + cc.z) * W_DIM + cc.w) * C_OUT_DIM;
    atomicAdd(out + base + c, g_vox[i]);
}

// ---------------------------------------------------------------------------
// Side stream + fork/join events: created ONCE on the first (uncaptured)
// correctness call; every call afterwards enqueues identical work, so the
// captured graph contains zero_kernel and compute_kernel as parallel branches.
// ---------------------------------------------------------------------------
static cudaStream_t g_s2 = nullptr;
static cudaEvent_t  g_fork = nullptr, g_join = nullptr;

extern "C" void kernel_launch(void* const* d_in, const int* in_sizes, int n_in,
                              void* d_out, int out_size) {
    const float* feat   = (const float*)d_in[0];
    const float* w1     = (const float*)d_in[1];
    const float* b1     = (const float*)d_in[2];
    const float* gamma1 = (const float*)d_in[3];
    const float* beta1  = (const float*)d_in[4];
    const float* mean1  = (const float*)d_in[5];
    const float* var1   = (const float*)d_in[6];
    const float* w2     = (const float*)d_in[7];
    const float* b2     = (const float*)d_in[8];
    const float* gamma2 = (const float*)d_in[9];
    const float* beta2  = (const float*)d_in[10];
    const float* mean2  = (const float*)d_in[11];
    const float* var2   = (const float*)d_in[12];
    const int*   coord  = (const int*)d_in[13];
    float* out = (float*)d_out;

    if (g_s2 == nullptr) {
        cudaStreamCreateWithFlags(&g_s2, cudaStreamNonBlocking);
        cudaEventCreateWithFlags(&g_fork, cudaEventDisableTiming);
        cudaEventCreateWithFlags(&g_join, cudaEventDisableTiming);
    }

    const int n4 = out_size / 4;

    // Fork: side stream branches off the capture (legacy) stream.
    cudaEventRecord(g_fork, 0);
    cudaStreamWaitEvent(g_s2, g_fork, 0);

    // Branch A (side stream): VFE compute into g_vox.
    compute_kernel<<<NCBLK, 256, 0, g_s2>>>(
        feat, w1, b1, gamma1, beta1, mean1, var1,
        w2, b2, gamma2, beta2, mean2, var2);
    cudaEventRecord(g_join, g_s2);

    // Branch B (main stream): zero the 720MB output grid.
    zero_kernel<<<NZBLK, 256>>>((float4*)out, n4);

    // Join: scatter depends on both branches.
    cudaStreamWaitEvent(0, g_join, 0);
    scatter_kernel<<<(K_VOX * C_OUT_DIM) / 256, 256>>>(coord, out);
}

// round 9
// speedup vs baseline: 2.3435x; 1.1866x over previous
#include <cuda_runtime.h>

// Problem constants (match reference)
#define K_VOX 12000
#define T_PTS 35
#define F_IN  7
#define D_DIM 10
#define H_DIM 400
#define W_DIM 352
#define C_OUT_DIM 128
#define EPSVAL 1e-3f

// Fused grid: period-8 interleave, 5 zero-role + 3 compute-role blocks.
// 1000 units -> 5000 zero blocks (1.28M threads, full store-MLP config)
//            -> 3000 compute blocks (4 voxels each = 12000 voxels).
#define NB_TOTAL 8000
#define N_ZERO_BLK 5000
#define ZERO_THREADS (N_ZERO_BLK * 256)

// Voxel-wise results staged here (fully overwritten each launch).
__device__ float g_vox[K_VOX * C_OUT_DIM];   // 6.1 MB

// ---------------------------------------------------------------------------
// Fused kernel: zero the 720MB output AND compute voxel features concurrently
// as interleaved blocks of one grid (the only overlap mechanism that works
// here). Compute results go to g_vox — no ordering hazard with the zeroing.
// ---------------------------------------------------------------------------
__global__ __launch_bounds__(256) void fused_kernel(
    const float* __restrict__ feat,     // [K, T, F]
    const float* __restrict__ w1,       // [F, 16]
    const float* __restrict__ b1,
    const float* __restrict__ gamma1, const float* __restrict__ beta1,
    const float* __restrict__ mean1,  const float* __restrict__ var1,
    const float* __restrict__ w2,       // [32, 64]
    const float* __restrict__ b2,
    const float* __restrict__ gamma2, const float* __restrict__ beta2,
    const float* __restrict__ mean2,  const float* __restrict__ var2,
    float*       __restrict__ out,      // [1, D, H, W, 128] — zeroed here
    int n4)                             // out_size / 4 (float4 count)
{
    const int bid = blockIdx.x;
    const int tid = threadIdx.x;
    const int r = bid & 7;

    if (r < 5) {
        // ---------------- Zero role ----------------
        const int zid = (bid >> 3) * 5 + r;
        float4* o4 = (float4*)out;
        const float4 z = make_float4(0.f, 0.f, 0.f, 0.f);
        for (int i = zid * 256 + tid; i < n4; i += ZERO_THREADS) o4[i] = z;
        return;
    }

    // ---------------- Compute role ----------------
    const int cid = (bid >> 3) * 3 + (r - 5);   // 0..2999
    const int g   = tid >> 6;                   // group 0..3 (one voxel each)
    const int v   = tid & 63;                   // output channel within group
    const int k   = cid * 4 + g;                // voxel id

    __shared__ float sw1[F_IN * 16];
    __shared__ float sb1[16], ss1[16], so1[16], spw1b[16];
    __shared__ float sfeat[4][T_PTS * F_IN];
    __shared__ int   smask[4][T_PTS];
    __shared__ __align__(16) float pw1s[4][T_PTS * 16];
    __shared__ float sagg1[4][16];

    // Block-invariant stage-1 params
    if (tid < F_IN * 16) sw1[tid] = w1[tid];
    if (tid < 16) {
        float s = gamma1[tid] * rsqrtf(var1[tid] + EPSVAL);
        float o = beta1[tid] - mean1[tid] * s;
        float bb = b1[tid];
        ss1[tid] = s; so1[tid] = o; sb1[tid] = bb;
        spw1b[tid] = fmaxf(bb, 0.f) * s + o;    // pw1 of a fully-masked point
    }

    // Per-thread stage-2 params (thread owns channels v and 64+v)
    const float s2v = gamma2[v] * rsqrtf(var2[v] + EPSVAL);
    const float o2v = beta2[v] - mean2[v] * s2v;
    const float b2v = b2[v];
    const float pw2b = fmaxf(b2v, 0.f) * s2v + o2v;   // pw2 of a masked point

    float w2A[16], w2B[16];
#pragma unroll
    for (int j = 0; j < 16; j++) {
        w2A[j] = __ldg(&w2[j * 64 + v]);
        w2B[j] = __ldg(&w2[(16 + j) * 64 + v]);
    }

    // Load this group's point features
    for (int i = v; i < T_PTS * F_IN; i += 64)
        sfeat[g][i] = feat[k * (T_PTS * F_IN) + i];
    __syncthreads();

    // Mask: point valid iff max over its features != 0
    if (v < T_PTS) {
        float m = sfeat[g][v * F_IN];
#pragma unroll
        for (int f = 1; f < F_IN; f++) m = fmaxf(m, sfeat[g][v * F_IN + f]);
        smask[g][v] = (m != 0.f) ? 1 : 0;
    }
    __syncthreads();

    // Stage 1: pw1_eff[t][u] (masked rows take the constant pw1b[u])
    for (int e = v; e < T_PTS * 16; e += 64) {
        const int t = e >> 4, u = e & 15;
        float val;
        if (smask[g][t]) {
            float d = sb1[u];
#pragma unroll
            for (int f = 0; f < F_IN; f++)
                d = fmaf(sfeat[g][t * F_IN + f], sw1[f * 16 + u], d);
            val = fmaxf(d, 0.f) * ss1[u] + so1[u];
        } else {
            val = spw1b[u];
        }
        pw1s[g][e] = val;
    }
    __syncthreads();

    // agg1[u] = max over ALL t of pw1_eff (reference maxes pre-mask)
    if (v < 16) {
        float m = pw1s[g][v];
        for (int t = 1; t < T_PTS; t++) m = fmaxf(m, pw1s[g][t * 16 + v]);
        sagg1[g][v] = m;
    }
    __syncthreads();

    // Stage 2: per-channel dot over valid rows
    float aggdot = 0.f;
#pragma unroll
    for (int j = 0; j < 16; j++) aggdot = fmaf(sagg1[g][j], w2B[j], aggdot);
    const float base2 = b2v + aggdot;

    float vmax = -3.4e38f, amax = -3.4e38f;
    int anyInvalid = 0, anyValid = 0;
    for (int t = 0; t < T_PTS; t++) {
        if (smask[g][t]) {
            anyValid = 1;
            const float4* row = (const float4*)(pw1s[g] + t * 16);
            float4 r0 = row[0], r1 = row[1], r2 = row[2], r3 = row[3];
            float d0 = base2, d1 = 0.f;
            d0 = fmaf(r0.x, w2A[0], d0);  d1 = fmaf(r0.y, w2A[1], d1);
            d0 = fmaf(r0.z, w2A[2], d0);  d1 = fmaf(r0.w, w2A[3], d1);
            d0 = fmaf(r1.x, w2A[4], d0);  d1 = fmaf(r1.y, w2A[5], d1);
            d0 = fmaf(r1.z, w2A[6], d0);  d1 = fmaf(r1.w, w2A[7], d1);
            d0 = fmaf(r2.x, w2A[8], d0);  d1 = fmaf(r2.y, w2A[9], d1);
            d0 = fmaf(r2.z, w2A[10], d0); d1 = fmaf(r2.w, w2A[11], d1);
            d0 = fmaf(r3.x, w2A[12], d0); d1 = fmaf(r3.y, w2A[13], d1);
            d0 = fmaf(r3.z, w2A[14], d0); d1 = fmaf(r3.w, w2A[15], d1);
            float pw2 = fmaxf(d0 + d1, 0.f) * s2v + o2v;
            vmax = fmaxf(vmax, pw2);
            amax = fmaxf(amax, pw2);
        } else {
            anyInvalid = 1;
        }
    }

    float outA, outB;
    if (!anyValid) {
        outA = 0.f; outB = 0.f;
    } else if (anyInvalid) {
        amax = fmaxf(amax, pw2b);
        outA = fmaxf(vmax, 0.f);
        outB = fmaxf(amax, 0.f);
    } else {
        outA = vmax; outB = amax;
    }

    g_vox[k * C_OUT_DIM + v]      = outA;
    g_vox[k * C_OUT_DIM + 64 + v] = outB;
}

// ---------------------------------------------------------------------------
// Scatter-add staged voxel results into the (now zeroed) grid.
// ---------------------------------------------------------------------------
__global__ __launch_bounds__(256) void scatter_kernel(
    const int* __restrict__ coord,      // [K, 4]
    float*     __restrict__ out)
{
    const int i = blockIdx.x * 256 + threadIdx.x;   // 0 .. K*128-1
    const int k = i >> 7;
    const int c = i & 127;
    const int4 cc = __ldg(&((const int4*)coord)[k]);
    const int base =
        (((cc.x * D_DIM + cc.y) * H_DIM + cc.z) * W_DIM + cc.w) * C_OUT_DIM;
    atomicAdd(out + base + c, g_vox[i]);
}

// ---------------------------------------------------------------------------
extern "C" void kernel_launch(void* const* d_in, const int* in_sizes, int n_in,
                              void* d_out, int out_size) {
    const float* feat   = (const float*)d_in[0];
    const float* w1     = (const float*)d_in[1];
    const float* b1     = (const float*)d_in[2];
    const float* gamma1 = (const float*)d_in[3];
    const float* beta1  = (const float*)d_in[4];
    const float* mean1  = (const float*)d_in[5];
    const float* var1   = (const float*)d_in[6];
    const float* w2     = (const float*)d_in[7];
    const float* b2     = (const float*)d_in[8];
    const float* gamma2 = (const float*)d_in[9];
    const float* beta2  = (const float*)d_in[10];
    const float* mean2  = (const float*)d_in[11];
    const float* var2   = (const float*)d_in[12];
    const int*   coord  = (const int*)d_in[13];
    float* out = (float*)d_out;

    const int n4 = out_size / 4;
    fused_kernel<<<NB_TOTAL, 256>>>(feat, w1, b1, gamma1, beta1, mean1, var1,
                                    w2, b2, gamma2, beta2, mean2, var2,
                                    out, n4);
    scatter_kernel<<<(K_VOX * C_OUT_DIM) / 256, 256>>>(coord, out);
}